// round 9
// baseline (speedup 1.0000x reference)
#include <cuda_runtime.h>
#include <math.h>

#define BATCH  1024
#define DIM    256
#define TSTEPS 128
#define HID    256
#define NOUT   64

__device__ float g_cur1[(size_t)TSTEPS * BATCH * HID];  // [t][b][h]
__device__ float g_WTin[DIM * HID];        // [d][h]
__device__ float g_WTh [HID * HID];        // [j][h]
__device__ float g_WTh1[HID * HID];        // [j][h]
__device__ float g_Wfa [HID * NOUT * 2];   // [j][o][2] (wf, wa)

typedef unsigned long long ull;

__device__ __forceinline__ void ffma2(ull& acc, ull a, ull b) {
    asm("fma.rn.f32x2 %0, %1, %2, %0;" : "+l"(acc) : "l"(a), "l"(b));
}
__device__ __forceinline__ ull mul2(ull a, ull b) {
    ull r; asm("mul.rn.f32x2 %0, %1, %2;" : "=l"(r) : "l"(a), "l"(b)); return r;
}
__device__ __forceinline__ ull add2(ull a, ull b) {
    ull r; asm("add.rn.f32x2 %0, %1, %2;" : "=l"(r) : "l"(a), "l"(b)); return r;
}
__device__ __forceinline__ ull pack2(float x, float y) {
    ull r; asm("mov.b64 %0, {%1, %2};" : "=l"(r) : "f"(x), "f"(y)); return r;
}
__device__ __forceinline__ void unpack2(ull v, float& x, float& y) {
    asm("mov.b64 {%0, %1}, %2;" : "=f"(x), "=f"(y) : "l"(v));
}
__device__ __forceinline__ float clamp01(float v) {
    return fminf(fmaxf(v, 0.0f), 1.0f);
}

__global__ void dummy_k() {}

// ---------------------------------------------------------------------------
__global__ void prep_weights(const float* __restrict__ W_in,
                             const float* __restrict__ W_h,
                             const float* __restrict__ W_h1,
                             const float* __restrict__ W_f,
                             const float* __restrict__ W_a) {
    if (blockIdx.z == 3) {
        int idx = (blockIdx.y * 8 + blockIdx.x) * 256 + threadIdx.y * 32 + threadIdx.x;
        int j = idx >> 6, oo = idx & 63;
        g_Wfa[idx * 2]     = W_f[oo * HID + j];
        g_Wfa[idx * 2 + 1] = W_a[oo * HID + j];
        return;
    }
    __shared__ float tile[32][33];
    const float* in; float* out;
    switch (blockIdx.z) {
        case 0:  in = W_in; out = g_WTin; break;
        case 1:  in = W_h;  out = g_WTh;  break;
        default: in = W_h1; out = g_WTh1; break;
    }
    int c0 = blockIdx.x * 32, r0 = blockIdx.y * 32;
    int tx = threadIdx.x, ty = threadIdx.y;
    #pragma unroll
    for (int k = 0; k < 32; k += 8)
        tile[ty + k][tx] = in[(r0 + ty + k) * 256 + (c0 + tx)];
    __syncthreads();
    #pragma unroll
    for (int k = 0; k < 32; k += 8)
        out[(c0 + ty + k) * 256 + (r0 + tx)] = tile[tx][ty + k];
}

// ---------------------------------------------------------------------------
// cur1[t][b][h] = sum_d x[b][d][t]*W_in[h][d].  CTA: 64 t x 256 h for one b.
// Thread: 2 h x 16 t (8 t-pairs). Chains serial over d ascending — bit-exact.
// grid (2, 1024), block 512, smem 64KB.
// ---------------------------------------------------------------------------
__global__ void __launch_bounds__(512) precompute_cur1(const float* __restrict__ x) {
    extern __shared__ __align__(16) float xS[];          // [256 d][64 t]
    ull* xsu = reinterpret_cast<ull*>(xS);               // [d][32 tp]
    const int tid = threadIdx.x;
    const int t0  = blockIdx.x * 64;
    const int b   = blockIdx.y;

    {   // stage: thread covers d = tid>>1, t-half = (tid&1)*32
        int d = tid >> 1, th = (tid & 1) * 32;
        const float4* xp = reinterpret_cast<const float4*>(
            x + ((size_t)b * DIM + d) * TSTEPS + t0 + th);
        #pragma unroll
        for (int q = 0; q < 8; ++q) {
            float4 v = __ldg(xp + q);
            xsu[d * 32 + th / 2 + 2 * q]     = pack2(v.x, v.y);
            xsu[d * 32 + th / 2 + 2 * q + 1] = pack2(v.z, v.w);
        }
    }
    __syncthreads();

    const int hp = tid & 127;        // h-pair: h0 = 2*hp
    const int tg = tid >> 7;         // 0..3 -> 16 t each
    ull acc[16];
    #pragma unroll
    for (int i = 0; i < 16; ++i) acc[i] = 0ull;

    const ull* gw = reinterpret_cast<const ull*>(g_WTin) + hp;
    #pragma unroll 1
    for (int blk = 0; blk < 32; ++blk) {
        ull wv[8];
        #pragma unroll
        for (int i = 0; i < 8; ++i)
            wv[i] = __ldg(gw + (blk * 8 + i) * 128);
        #pragma unroll
        for (int i = 0; i < 8; ++i) {
            const int j = blk * 8 + i;
            float w0, w1; unpack2(wv[i], w0, w1);
            ull wa = pack2(w0, w0), wb = pack2(w1, w1);
            const ull* xr = xsu + j * 32 + tg * 8;
            #pragma unroll
            for (int tp = 0; tp < 8; ++tp) {
                ull xv = xr[tp];
                ffma2(acc[tp],     xv, wa);
                ffma2(acc[8 + tp], xv, wb);
            }
        }
    }
    // store: per t, (h0,h0+1) as one STG.64 (coalesced across lanes)
    #pragma unroll
    for (int tp = 0; tp < 8; ++tp) {
        float a0, a1, b0, b1;
        unpack2(acc[tp], a0, a1);        // h0: t even, t odd
        unpack2(acc[8 + tp], b0, b1);    // h1
        int t = t0 + tg * 16 + 2 * tp;
        ull* dst0 = reinterpret_cast<ull*>(
            g_cur1 + ((size_t)t * BATCH + b) * HID + 2 * hp);
        ull* dst1 = reinterpret_cast<ull*>(
            g_cur1 + ((size_t)(t + 1) * BATCH + b) * HID + 2 * hp);
        *dst0 = pack2(a0, b0);
        *dst1 = pack2(a1, b1);
    }
}

// ---------------------------------------------------------------------------
// Hidden layer, 2 h per thread (4 warps cover 256 h), 8 rows. Bit-exact.
// ---------------------------------------------------------------------------
__device__ __forceinline__ void layer2h(
    const ull* __restrict__ gWp, const float* sIn,
    float bias0, float bias1, float bc0, float bc1, float thr0, float thr1,
    float* m /*[hh*8+r]*/, float* sOut, int hp)
{
    ull acc[8];
    #pragma unroll
    for (int i = 0; i < 8; ++i) acc[i] = 0ull;
    const ull* gbase = gWp + hp;
    #pragma unroll 1
    for (int blk = 0; blk < 32; ++blk) {
        ull wv[8];
        #pragma unroll
        for (int i = 0; i < 8; ++i)
            wv[i] = __ldg(gbase + (blk * 8 + i) * 128);
        #pragma unroll
        for (int i = 0; i < 8; ++i) {
            const int j = blk * 8 + i;
            float w0, w1; unpack2(wv[i], w0, w1);
            ull wa = pack2(w0, w0), wb = pack2(w1, w1);
            const ulonglong2* sp = reinterpret_cast<const ulonglong2*>(sIn + j * 8);
            ulonglong2 sA = sp[0], sB = sp[1];
            ffma2(acc[0], sA.x, wa); ffma2(acc[1], sA.y, wa);
            ffma2(acc[2], sB.x, wa); ffma2(acc[3], sB.y, wa);
            ffma2(acc[4], sA.x, wb); ffma2(acc[5], sA.y, wb);
            ffma2(acc[6], sB.x, wb); ffma2(acc[7], sB.y, wb);
        }
    }
    #pragma unroll
    for (int hh = 0; hh < 2; ++hh) {
        float bias = hh ? bias1 : bias0;
        float bc   = hh ? bc1 : bc0;
        float thr  = hh ? thr1 : thr0;
        ull svp[4];
        #pragma unroll
        for (int p = 0; p < 4; ++p) {
            float c0, c1; unpack2(acc[hh * 4 + p], c0, c1);
            float* mm = m + hh * 8 + 2 * p;
            float ca = __fadd_rn(c0, bias);
            float cb = __fadd_rn(c1, bias);
            float ra = (mm[0] > thr) ? thr : 0.0f;     // reset from PREV mem
            float rb = (mm[1] > thr) ? thr : 0.0f;
            float na = __fsub_rn(__fadd_rn(__fmul_rn(bc, mm[0]), ca), ra);
            float nb = __fsub_rn(__fadd_rn(__fmul_rn(bc, mm[1]), cb), rb);
            mm[0] = na; mm[1] = nb;
            svp[p] = pack2((na > thr) ? 1.0f : 0.0f, (nb > thr) ? 1.0f : 0.0f);
        }
        ulonglong2* op = reinterpret_cast<ulonglong2*>(sOut + (2 * hp + hh) * 8);
        ulonglong2 v;
        v.x = svp[0]; v.y = svp[1]; op[0] = v;
        v.x = svp[2]; v.y = svp[3]; op[1] = v;
    }
}

// ---------------------------------------------------------------------------
// Recurrent kernel: 128 CTAs x 384 threads.
//  A (warps 0-3, 128t, 2h/thread): LIF1 -> L2 -> L3 for step k
//  B (warps 4-11, 256t): output-LI GEMM for step k-1 from double-buffered s3
// ---------------------------------------------------------------------------
#define SMEM_FLOATS (HID * NOUT * 2 + 4 * 2048 + 4096)
#define SMEM_BYTES  (SMEM_FLOATS * 4)

__global__ void __launch_bounds__(384, 1) snn_rec(
    const float* __restrict__ b_in,  const float* __restrict__ beta1,
    const float* __restrict__ thr1,
    const float* __restrict__ b_h,   const float* __restrict__ beta2,
    const float* __restrict__ thr2,
    const float* __restrict__ b_h1,
    const float* __restrict__ b_f,   const float* __restrict__ beta_f,
    const float* __restrict__ b_a,   const float* __restrict__ beta_a,
    float* __restrict__ out)
{
    extern __shared__ __align__(16) float dsm[];
    float* sWfa = dsm;                         // 32768 floats
    float* s1P  = sWfa + HID * NOUT * 2;
    float* s2P  = s1P + 2048;
    float* s3a  = s2P + 2048;
    float* s3b  = s3a + 2048;
    ull*   scr  = reinterpret_cast<ull*>(s3b + 2048);   // 2048 ull

    const int tid = threadIdx.x;
    const int b0  = blockIdx.x * 8;

    for (int i = tid; i < HID * NOUT * 2; i += 384)
        sWfa[i] = g_Wfa[i];

    if (tid < 128) {
        // ===================== A role =====================
        const int hp = tid;
        const int h0 = 2 * hp, h1 = h0 + 1;
        const float bin0 = b_in[h0],  bin1 = b_in[h1];
        const float b1c0 = clamp01(beta1[h0]), b1c1 = clamp01(beta1[h1]);
        const float t10 = thr1[h0],  t11 = thr1[h1];
        const float bh0 = b_h[h0],   bh1 = b_h[h1];
        const float b2c0 = clamp01(beta2[h0]), b2c1 = clamp01(beta2[h1]);
        const float t20 = thr2[h0],  t21 = thr2[h1];
        const float bh10 = b_h1[h0], bh11 = b_h1[h1];

        float m1[16], m2[16], m3[16];
        #pragma unroll
        for (int i = 0; i < 16; ++i) { m1[i] = 0.f; m2[i] = 0.f; m3[i] = 0.f; }

        ull c1p[8];   // (h0,h1) per row
        #pragma unroll
        for (int r = 0; r < 8; ++r)
            c1p[r] = __ldg(reinterpret_cast<const ull*>(
                g_cur1 + ((size_t)0 * BATCH + b0 + r) * HID + h0));

        __syncthreads();   // Wfa ready

        const ull* gWh  = reinterpret_cast<const ull*>(g_WTh);
        const ull* gWh1 = reinterpret_cast<const ull*>(g_WTh1);

        for (int k = 0; k <= TSTEPS; ++k) {
            if (k < TSTEPS) {
                // LIF layer 1 -> s1P
                ull svp0[4], svp1[4];
                #pragma unroll
                for (int r = 0; r < 8; ++r) {
                    float c0, c1; unpack2(c1p[r], c0, c1);
                    float ca = __fadd_rn(c0, bin0);
                    float cb = __fadd_rn(c1, bin1);
                    float ra = (m1[r] > t10) ? t10 : 0.0f;
                    float rb = (m1[8 + r] > t11) ? t11 : 0.0f;
                    float na = __fsub_rn(__fadd_rn(__fmul_rn(b1c0, m1[r]), ca), ra);
                    float nb = __fsub_rn(__fadd_rn(__fmul_rn(b1c1, m1[8 + r]), cb), rb);
                    m1[r] = na; m1[8 + r] = nb;
                    float s0 = (na > t10) ? 1.0f : 0.0f;
                    float s1v = (nb > t11) ? 1.0f : 0.0f;
                    if (r & 1) {
                        float p0, p1;
                        unpack2(svp0[r >> 1], p0, p1);   // placeholder
                    }
                    // accumulate into packed lanes below
                    reinterpret_cast<float*>(svp0)[r] = s0;
                    reinterpret_cast<float*>(svp1)[r] = s1v;
                }
                {
                    ulonglong2* op0 = reinterpret_cast<ulonglong2*>(s1P + h0 * 8);
                    ulonglong2* op1 = reinterpret_cast<ulonglong2*>(s1P + h1 * 8);
                    ulonglong2 v;
                    v.x = svp0[0]; v.y = svp0[1]; op0[0] = v;
                    v.x = svp0[2]; v.y = svp0[3]; op0[1] = v;
                    v.x = svp1[0]; v.y = svp1[1]; op1[0] = v;
                    v.x = svp1[2]; v.y = svp1[3]; op1[1] = v;
                }
                if (k + 1 < TSTEPS) {
                    #pragma unroll
                    for (int r = 0; r < 8; ++r)
                        c1p[r] = __ldg(reinterpret_cast<const ull*>(
                            g_cur1 + ((size_t)(k + 1) * BATCH + b0 + r) * HID + h0));
                }
                asm volatile("bar.sync 1, 128;" ::: "memory");

                layer2h(gWh, s1P, bh0, bh1, b2c0, b2c1, t20, t21, m2, s2P, hp);
                asm volatile("bar.sync 1, 128;" ::: "memory");

                float* s3 = (k & 1) ? s3b : s3a;
                layer2h(gWh1, s2P, bh10, bh11, b2c0, b2c1, t20, t21, m3, s3, hp);
            }
            __syncthreads();   // publish s3(k) to B
        }
    } else {
        // ===================== B role =====================
        const int bt = tid - 128;
        const int o  = bt & 63;
        const int q  = bt >> 6;                 // j-slice; owns rows 2q,2q+1
        const ull bias_fa = pack2(b_f[o], b_a[o]);
        const ull beta_fa = pack2(clamp01(beta_f[o]), clamp01(beta_a[o]));
        ull macc0 = pack2(0.f, 0.f), macc1 = macc0;

        __syncthreads();   // Wfa ready

        for (int k = 0; k <= TSTEPS; ++k) {
            if (k >= 1) {
                const float* s3 = ((k - 1) & 1) ? s3b : s3a;
                ull accF[4] = {0ull, 0ull, 0ull, 0ull};
                ull accA[4] = {0ull, 0ull, 0ull, 0ull};
                const ull* wrow = reinterpret_cast<const ull*>(sWfa);
                const int j0 = q * 64;
                #pragma unroll 8
                for (int jj = 0; jj < 64; ++jj) {
                    int j = j0 + jj;
                    ull w = wrow[j * 64 + o];
                    float wf, wa; unpack2(w, wf, wa);
                    ull wf2 = pack2(wf, wf), wa2 = pack2(wa, wa);
                    const ulonglong2* sp =
                        reinterpret_cast<const ulonglong2*>(s3 + j * 8);
                    ulonglong2 sA = sp[0], sB = sp[1];
                    ffma2(accF[0], sA.x, wf2); ffma2(accF[1], sA.y, wf2);
                    ffma2(accF[2], sB.x, wf2); ffma2(accF[3], sB.y, wf2);
                    ffma2(accA[0], sA.x, wa2); ffma2(accA[1], sA.y, wa2);
                    ffma2(accA[2], sB.x, wa2); ffma2(accA[3], sB.y, wa2);
                }
                #pragma unroll
                for (int r2 = 0; r2 < 4; ++r2) {
                    scr[r2 * 256 + q * 64 + o]        = accF[r2];
                    scr[1024 + r2 * 256 + q * 64 + o] = accA[r2];
                }
                asm volatile("bar.sync 2, 256;" ::: "memory");
                ull Fs = pack2(0.f, 0.f), As = Fs;
                #pragma unroll
                for (int qq = 0; qq < 4; ++qq) {
                    Fs = add2(Fs, scr[q * 256 + qq * 64 + o]);
                    As = add2(As, scr[1024 + q * 256 + qq * 64 + o]);
                }
                float f0, f1, a0, a1;
                unpack2(Fs, f0, f1);
                unpack2(As, a0, a1);
                macc0 = add2(mul2(beta_fa, macc0), add2(pack2(f0, a0), bias_fa));
                macc1 = add2(mul2(beta_fa, macc1), add2(pack2(f1, a1), bias_fa));
            }
            __syncthreads();
        }

        float mf0, ma0, mf1, ma1;
        unpack2(macc0, mf0, ma0);
        unpack2(macc1, mf1, ma1);
        int row = b0 + 2 * q;
        out[(size_t)row * NOUT + o]                              = 1.0f / (1.0f + expf(-mf0));
        out[(size_t)(row + 1) * NOUT + o]                        = 1.0f / (1.0f + expf(-mf1));
        out[(size_t)BATCH * NOUT + (size_t)row * NOUT + o]       = 1.0f / (1.0f + expf(-ma0));
        out[(size_t)BATCH * NOUT + (size_t)(row + 1) * NOUT + o] = 1.0f / (1.0f + expf(-ma1));
    }
}

// ---------------------------------------------------------------------------
extern "C" void kernel_launch(void* const* d_in, const int* in_sizes, int n_in,
                              void* d_out, int out_size) {
    const float* x      = (const float*)d_in[0];
    const float* W_in   = (const float*)d_in[1];
    const float* b_in   = (const float*)d_in[2];
    const float* beta1  = (const float*)d_in[3];
    const float* thr1   = (const float*)d_in[4];
    const float* W_h    = (const float*)d_in[5];
    const float* b_h    = (const float*)d_in[6];
    const float* beta2  = (const float*)d_in[7];
    const float* thr2   = (const float*)d_in[8];
    const float* W_h1   = (const float*)d_in[9];
    const float* b_h1   = (const float*)d_in[10];
    const float* W_f    = (const float*)d_in[11];
    const float* b_f    = (const float*)d_in[12];
    const float* beta_f = (const float*)d_in[13];
    const float* W_a    = (const float*)d_in[14];
    const float* b_a    = (const float*)d_in[15];
    const float* beta_a = (const float*)d_in[16];
    float* out = (float*)d_out;

    cudaFuncSetAttribute(snn_rec, cudaFuncAttributeMaxDynamicSharedMemorySize,
                         SMEM_BYTES);
    cudaFuncSetAttribute(precompute_cur1,
                         cudaFuncAttributeMaxDynamicSharedMemorySize, 65536);

    dummy_k<<<1, 1>>>();
    prep_weights<<<dim3(8, 8, 4), dim3(32, 8)>>>(W_in, W_h, W_h1, W_f, W_a);
    precompute_cur1<<<dim3(2, BATCH), 512, 65536>>>(x);
    snn_rec<<<BATCH / 8, 384, SMEM_BYTES>>>(b_in, beta1, thr1, b_h, beta2, thr2,
                                            b_h1, b_f, beta_f, b_a, beta_a, out);
}

// round 10
// speedup vs baseline: 1.3717x; 1.3717x over previous
#include <cuda_runtime.h>
#include <math.h>

#define BATCH  1024
#define DIM    256
#define TSTEPS 128
#define HID    256
#define NOUT   64
#define JC     80     // j-rows of each hidden matrix cached in smem

__device__ float g_cur1[(size_t)TSTEPS * BATCH * HID];  // [t][b][h]
__device__ float g_WTin[DIM * HID];        // [d][h]
__device__ float g_WTh [HID * HID];        // [j][h]
__device__ float g_WTh1[HID * HID];        // [j][h]
__device__ float g_Wfa [HID * NOUT * 2];   // [j][o][2] (wf, wa)

typedef unsigned long long ull;

__device__ __forceinline__ void ffma2(ull& acc, ull a, ull b) {
    asm("fma.rn.f32x2 %0, %1, %2, %0;" : "+l"(acc) : "l"(a), "l"(b));
}
__device__ __forceinline__ ull mul2(ull a, ull b) {
    ull r; asm("mul.rn.f32x2 %0, %1, %2;" : "=l"(r) : "l"(a), "l"(b)); return r;
}
__device__ __forceinline__ ull add2(ull a, ull b) {
    ull r; asm("add.rn.f32x2 %0, %1, %2;" : "=l"(r) : "l"(a), "l"(b)); return r;
}
__device__ __forceinline__ ull pack2(float x, float y) {
    ull r; asm("mov.b64 %0, {%1, %2};" : "=l"(r) : "f"(x), "f"(y)); return r;
}
__device__ __forceinline__ void unpack2(ull v, float& x, float& y) {
    asm("mov.b64 {%0, %1}, %2;" : "=f"(x), "=f"(y) : "l"(v));
}
__device__ __forceinline__ float clamp01(float v) {
    return fminf(fmaxf(v, 0.0f), 1.0f);
}

__global__ void dummy_k() {}

// ---------------------------------------------------------------------------
__global__ void prep_weights(const float* __restrict__ W_in,
                             const float* __restrict__ W_h,
                             const float* __restrict__ W_h1,
                             const float* __restrict__ W_f,
                             const float* __restrict__ W_a) {
    if (blockIdx.z == 3) {
        int idx = (blockIdx.y * 8 + blockIdx.x) * 256 + threadIdx.y * 32 + threadIdx.x;
        int j = idx >> 6, oo = idx & 63;
        g_Wfa[idx * 2]     = W_f[oo * HID + j];
        g_Wfa[idx * 2 + 1] = W_a[oo * HID + j];
        return;
    }
    __shared__ float tile[32][33];
    const float* in; float* out;
    switch (blockIdx.z) {
        case 0:  in = W_in; out = g_WTin; break;
        case 1:  in = W_h;  out = g_WTh;  break;
        default: in = W_h1; out = g_WTh1; break;
    }
    int c0 = blockIdx.x * 32, r0 = blockIdx.y * 32;
    int tx = threadIdx.x, ty = threadIdx.y;
    #pragma unroll
    for (int k = 0; k < 32; k += 8)
        tile[ty + k][tx] = in[(r0 + ty + k) * 256 + (c0 + tx)];
    __syncthreads();
    #pragma unroll
    for (int k = 0; k < 32; k += 8)
        out[(c0 + ty + k) * 256 + (r0 + tx)] = tile[tx][ty + k];
}

// ---------------------------------------------------------------------------
// cur1[t][b][h] = sum_d x[b][d][t]*W_in[h][d].  (unchanged from R8 — works)
// ---------------------------------------------------------------------------
__global__ void __launch_bounds__(512) precompute_cur1(const float* __restrict__ x) {
    extern __shared__ __align__(16) float xS[];
    ull* xsu = reinterpret_cast<ull*>(xS);
    const int tid = threadIdx.x;
    const int t0  = blockIdx.x * 64;
    const int b   = blockIdx.y;

    {
        int d = tid >> 1, th = (tid & 1) * 32;
        const float4* xp = reinterpret_cast<const float4*>(
            x + ((size_t)b * DIM + d) * TSTEPS + t0 + th);
        #pragma unroll
        for (int q = 0; q < 8; ++q) {
            float4 v = __ldg(xp + q);
            xsu[d * 32 + th / 2 + 2 * q]     = pack2(v.x, v.y);
            xsu[d * 32 + th / 2 + 2 * q + 1] = pack2(v.z, v.w);
        }
    }
    __syncthreads();

    const int hp = tid & 127;
    const int tg = tid >> 7;
    ull acc[16];
    #pragma unroll
    for (int i = 0; i < 16; ++i) acc[i] = 0ull;

    const ull* gw = reinterpret_cast<const ull*>(g_WTin) + hp;
    #pragma unroll 1
    for (int blk = 0; blk < 32; ++blk) {
        ull wv[8];
        #pragma unroll
        for (int i = 0; i < 8; ++i)
            wv[i] = __ldg(gw + (blk * 8 + i) * 128);
        #pragma unroll
        for (int i = 0; i < 8; ++i) {
            const int j = blk * 8 + i;
            float w0, w1; unpack2(wv[i], w0, w1);
            ull wa = pack2(w0, w0), wb = pack2(w1, w1);
            const ull* xr = xsu + j * 32 + tg * 8;
            #pragma unroll
            for (int tp = 0; tp < 8; ++tp) {
                ull xv = xr[tp];
                ffma2(acc[tp],     xv, wa);
                ffma2(acc[8 + tp], xv, wb);
            }
        }
    }
    #pragma unroll
    for (int tp = 0; tp < 8; ++tp) {
        float a0, a1, b0, b1;
        unpack2(acc[tp], a0, a1);
        unpack2(acc[8 + tp], b0, b1);
        int t = t0 + tg * 16 + 2 * tp;
        *reinterpret_cast<ull*>(g_cur1 + ((size_t)t * BATCH + b) * HID + 2 * hp)
            = pack2(a0, b0);
        *reinterpret_cast<ull*>(g_cur1 + ((size_t)(t + 1) * BATCH + b) * HID + 2 * hp)
            = pack2(a1, b1);
    }
}

// ---------------------------------------------------------------------------
// Uncached-j helpers: blocks of 16, register double-buffered.
// ---------------------------------------------------------------------------
__device__ __forceinline__ void ldblk16(ull* buf, const ull* gb, int blk) {
    #pragma unroll
    for (int i = 0; i < 16; ++i)
        buf[i] = __ldg(gb + (JC + blk * 16 + i) * 128);
}
__device__ __forceinline__ void useblk16(const ull* buf, const float* sInb,
                                         int blk, ull* acc) {
    #pragma unroll
    for (int i = 0; i < 16; ++i) {
        float w0, w1; unpack2(buf[i], w0, w1);
        ull wa = pack2(w0, w0), wb = pack2(w1, w1);
        ulonglong2 sv = *reinterpret_cast<const ulonglong2*>(
            sInb + (JC + blk * 16 + i) * 8);
        ffma2(acc[0], sv.x, wa); ffma2(acc[1], sv.y, wa);
        ffma2(acc[2], sv.x, wb); ffma2(acc[3], sv.y, wb);
    }
}

// ---------------------------------------------------------------------------
// Hidden layer: thread owns 2 h x 4 rows. Chains serial over j — bit-exact.
// ---------------------------------------------------------------------------
__device__ __forceinline__ void layerX(
    const float* sW, const ull* __restrict__ gWp, const float* sIn,
    int rg, int hp,
    float bias0, float bias1, float bc0, float bc1, float thr0, float thr1,
    float* m /*[hh*4+r]*/, float* sOut)
{
    ull acc[4] = {0ull, 0ull, 0ull, 0ull};
    const float* sInb = sIn + rg * 4;
    const ull* sWp = reinterpret_cast<const ull*>(sW) + hp;
    #pragma unroll 8
    for (int j = 0; j < JC; ++j) {
        float w0, w1; unpack2(sWp[j * 128], w0, w1);
        ull wa = pack2(w0, w0), wb = pack2(w1, w1);
        ulonglong2 sv = *reinterpret_cast<const ulonglong2*>(sInb + j * 8);
        ffma2(acc[0], sv.x, wa); ffma2(acc[1], sv.y, wa);
        ffma2(acc[2], sv.x, wb); ffma2(acc[3], sv.y, wb);
    }
    // 176 uncached rows = 11 blocks of 16, double-buffered
    const ull* gb = gWp + hp;
    ull bufA[16], bufB[16];
    ldblk16(bufA, gb, 0);
    #pragma unroll
    for (int b2 = 0; b2 < 5; ++b2) {
        ldblk16(bufB, gb, 2 * b2 + 1);
        useblk16(bufA, sInb, 2 * b2, acc);
        ldblk16(bufA, gb, 2 * b2 + 2);      // b2=4 -> blk 10 (last)
        useblk16(bufB, sInb, 2 * b2 + 1, acc);
    }
    useblk16(bufA, sInb, 10, acc);

    #pragma unroll
    for (int hh = 0; hh < 2; ++hh) {
        float bias = hh ? bias1 : bias0;
        float bc   = hh ? bc1 : bc0;
        float thr  = hh ? thr1 : thr0;
        ull svp[2];
        #pragma unroll
        for (int p = 0; p < 2; ++p) {
            float c0, c1; unpack2(acc[hh * 2 + p], c0, c1);
            float* mm = m + hh * 4 + 2 * p;
            float ca = __fadd_rn(c0, bias);
            float cb = __fadd_rn(c1, bias);
            float ra = (mm[0] > thr) ? thr : 0.0f;     // reset from PREV mem
            float rb = (mm[1] > thr) ? thr : 0.0f;
            float na = __fsub_rn(__fadd_rn(__fmul_rn(bc, mm[0]), ca), ra);
            float nb = __fsub_rn(__fadd_rn(__fmul_rn(bc, mm[1]), cb), rb);
            mm[0] = na; mm[1] = nb;
            svp[p] = pack2((na > thr) ? 1.0f : 0.0f, (nb > thr) ? 1.0f : 0.0f);
        }
        ulonglong2 v; v.x = svp[0]; v.y = svp[1];
        *reinterpret_cast<ulonglong2*>(sOut + (2 * hp + hh) * 8 + rg * 4) = v;
    }
}

// ---------------------------------------------------------------------------
// Recurrent kernel: 128 CTAs x 512 threads.
//  A (warps 0-7): thread = (hp = tid&127, rg = tid>>7): 2 h x 4 rows.
//      LIF1(k) -> s1P; L2(k): s1P->s2P; L3(k): s2P->s3[k&1]
//  B (warps 8-15): output-LI GEMM for step k-1; Wfa read from global (L2-hot)
// smem: sWh 80KB | sWh1 80KB | s1P s2P s3a s3b 8KB ea | scr 16KB = 208KB
// ---------------------------------------------------------------------------
#define SMEM_FLOATS (2 * JC * HID + 4 * 2048 + 4096)
#define SMEM_BYTES  (SMEM_FLOATS * 4)

__global__ void __launch_bounds__(512, 1) snn_rec(
    const float* __restrict__ b_in,  const float* __restrict__ beta1,
    const float* __restrict__ thr1,
    const float* __restrict__ b_h,   const float* __restrict__ beta2,
    const float* __restrict__ thr2,
    const float* __restrict__ b_h1,
    const float* __restrict__ b_f,   const float* __restrict__ beta_f,
    const float* __restrict__ b_a,   const float* __restrict__ beta_a,
    float* __restrict__ out)
{
    extern __shared__ __align__(16) float dsm[];
    float* sWh  = dsm;                      // JC*256
    float* sWh1 = sWh + JC * HID;           // JC*256
    float* s1P  = sWh1 + JC * HID;          // 2048
    float* s2P  = s1P + 2048;
    float* s3a  = s2P + 2048;
    float* s3b  = s3a + 2048;
    ull*   scr  = reinterpret_cast<ull*>(s3b + 2048);   // 2048 ull

    const int tid = threadIdx.x;
    const int b0  = blockIdx.x * 8;

    // one-time weight cache fill (j-rows 0..JC-1 of each matrix)
    for (int i = tid; i < JC * HID; i += 512) {
        sWh[i]  = g_WTh[i];
        sWh1[i] = g_WTh1[i];
    }

    if (tid < 256) {
        // ===================== A role =====================
        const int hp = tid & 127;
        const int rg = tid >> 7;             // row group: rows b0+rg*4 .. +3
        const int h0 = 2 * hp, h1 = h0 + 1;
        const float bin0 = b_in[h0],  bin1 = b_in[h1];
        const float b1c0 = clamp01(beta1[h0]), b1c1 = clamp01(beta1[h1]);
        const float t10 = thr1[h0],  t11 = thr1[h1];
        const float bh0 = b_h[h0],   bh1 = b_h[h1];
        const float b2c0 = clamp01(beta2[h0]), b2c1 = clamp01(beta2[h1]);
        const float t20 = thr2[h0],  t21 = thr2[h1];
        const float bh10 = b_h1[h0], bh11 = b_h1[h1];

        float m1[8], m2[8], m3[8];
        #pragma unroll
        for (int i = 0; i < 8; ++i) { m1[i] = 0.f; m2[i] = 0.f; m3[i] = 0.f; }

        const int rowbase = b0 + rg * 4;
        ull c1p[4];
        #pragma unroll
        for (int r = 0; r < 4; ++r)
            c1p[r] = __ldg(reinterpret_cast<const ull*>(
                g_cur1 + ((size_t)0 * BATCH + rowbase + r) * HID + h0));

        __syncthreads();   // weight caches ready

        const ull* gWh  = reinterpret_cast<const ull*>(g_WTh);
        const ull* gWh1 = reinterpret_cast<const ull*>(g_WTh1);

        for (int k = 0; k <= TSTEPS; ++k) {
            if (k < TSTEPS) {
                // ---- LIF layer 1: 2h x 4 rows ----
                ull sv0[2], sv1[2];
                #pragma unroll
                for (int p = 0; p < 2; ++p) {
                    float ca0, cb0, ca1, cb1;
                    unpack2(c1p[2 * p],     ca0, ca1);   // row 2p:   (h0, h1)
                    unpack2(c1p[2 * p + 1], cb0, cb1);   // row 2p+1: (h0, h1)
                    // h0, rows 2p / 2p+1
                    float x0 = __fadd_rn(ca0, bin0);
                    float x1 = __fadd_rn(cb0, bin0);
                    float r0 = (m1[2 * p] > t10) ? t10 : 0.0f;
                    float r1 = (m1[2 * p + 1] > t10) ? t10 : 0.0f;
                    float n0 = __fsub_rn(__fadd_rn(__fmul_rn(b1c0, m1[2 * p]), x0), r0);
                    float n1 = __fsub_rn(__fadd_rn(__fmul_rn(b1c0, m1[2 * p + 1]), x1), r1);
                    m1[2 * p] = n0; m1[2 * p + 1] = n1;
                    sv0[p] = pack2((n0 > t10) ? 1.0f : 0.0f, (n1 > t10) ? 1.0f : 0.0f);
                    // h1
                    float y0 = __fadd_rn(ca1, bin1);
                    float y1 = __fadd_rn(cb1, bin1);
                    float s0 = (m1[4 + 2 * p] > t11) ? t11 : 0.0f;
                    float s1 = (m1[4 + 2 * p + 1] > t11) ? t11 : 0.0f;
                    float q0 = __fsub_rn(__fadd_rn(__fmul_rn(b1c1, m1[4 + 2 * p]), y0), s0);
                    float q1 = __fsub_rn(__fadd_rn(__fmul_rn(b1c1, m1[4 + 2 * p + 1]), y1), s1);
                    m1[4 + 2 * p] = q0; m1[4 + 2 * p + 1] = q1;
                    sv1[p] = pack2((q0 > t11) ? 1.0f : 0.0f, (q1 > t11) ? 1.0f : 0.0f);
                }
                {
                    ulonglong2 v;
                    v.x = sv0[0]; v.y = sv0[1];
                    *reinterpret_cast<ulonglong2*>(s1P + h0 * 8 + rg * 4) = v;
                    v.x = sv1[0]; v.y = sv1[1];
                    *reinterpret_cast<ulonglong2*>(s1P + h1 * 8 + rg * 4) = v;
                }
                if (k + 1 < TSTEPS) {
                    #pragma unroll
                    for (int r = 0; r < 4; ++r)
                        c1p[r] = __ldg(reinterpret_cast<const ull*>(
                            g_cur1 + ((size_t)(k + 1) * BATCH + rowbase + r) * HID + h0));
                }
                asm volatile("bar.sync 1, 256;" ::: "memory");

                layerX(sWh, gWh, s1P, rg, hp,
                       bh0, bh1, b2c0, b2c1, t20, t21, m2, s2P);
                asm volatile("bar.sync 1, 256;" ::: "memory");

                float* s3 = (k & 1) ? s3b : s3a;
                layerX(sWh1, gWh1, s2P, rg, hp,
                       bh10, bh11, b2c0, b2c1, t20, t21, m3, s3);  // bug preserved
            }
            __syncthreads();   // publish s3(k) to B
        }
    } else {
        // ===================== B role =====================
        const int bt = tid - 256;
        const int o  = bt & 63;
        const int q  = bt >> 6;
        const ull bias_fa = pack2(b_f[o], b_a[o]);
        const ull beta_fa = pack2(clamp01(beta_f[o]), clamp01(beta_a[o]));
        ull macc0 = pack2(0.f, 0.f), macc1 = macc0;
        const ull* wrow = reinterpret_cast<const ull*>(g_Wfa);

        __syncthreads();

        for (int k = 0; k <= TSTEPS; ++k) {
            if (k >= 1) {
                const float* s3 = ((k - 1) & 1) ? s3b : s3a;
                ull accF[4] = {0ull, 0ull, 0ull, 0ull};
                ull accA[4] = {0ull, 0ull, 0ull, 0ull};
                const int j0 = q * 64;
                #pragma unroll 8
                for (int jj = 0; jj < 64; ++jj) {
                    int j = j0 + jj;
                    ull w = __ldg(wrow + j * 64 + o);
                    float wf, wa; unpack2(w, wf, wa);
                    ull wf2 = pack2(wf, wf), wa2 = pack2(wa, wa);
                    const ulonglong2* sp =
                        reinterpret_cast<const ulonglong2*>(s3 + j * 8);
                    ulonglong2 sA = sp[0], sB = sp[1];
                    ffma2(accF[0], sA.x, wf2); ffma2(accF[1], sA.y, wf2);
                    ffma2(accF[2], sB.x, wf2); ffma2(accF[3], sB.y, wf2);
                    ffma2(accA[0], sA.x, wa2); ffma2(accA[1], sA.y, wa2);
                    ffma2(accA[2], sB.x, wa2); ffma2(accA[3], sB.y, wa2);
                }
                #pragma unroll
                for (int r2 = 0; r2 < 4; ++r2) {
                    scr[r2 * 256 + q * 64 + o]        = accF[r2];
                    scr[1024 + r2 * 256 + q * 64 + o] = accA[r2];
                }
                asm volatile("bar.sync 2, 256;" ::: "memory");
                ull Fs = pack2(0.f, 0.f), As = Fs;
                #pragma unroll
                for (int qq = 0; qq < 4; ++qq) {
                    Fs = add2(Fs, scr[q * 256 + qq * 64 + o]);
                    As = add2(As, scr[1024 + q * 256 + qq * 64 + o]);
                }
                float f0, f1, a0, a1;
                unpack2(Fs, f0, f1);
                unpack2(As, a0, a1);
                macc0 = add2(mul2(beta_fa, macc0), add2(pack2(f0, a0), bias_fa));
                macc1 = add2(mul2(beta_fa, macc1), add2(pack2(f1, a1), bias_fa));
            }
            __syncthreads();
        }

        float mf0, ma0, mf1, ma1;
        unpack2(macc0, mf0, ma0);
        unpack2(macc1, mf1, ma1);
        int row = b0 + 2 * q;
        out[(size_t)row * NOUT + o]                              = 1.0f / (1.0f + expf(-mf0));
        out[(size_t)(row + 1) * NOUT + o]                        = 1.0f / (1.0f + expf(-mf1));
        out[(size_t)BATCH * NOUT + (size_t)row * NOUT + o]       = 1.0f / (1.0f + expf(-ma0));
        out[(size_t)BATCH * NOUT + (size_t)(row + 1) * NOUT + o] = 1.0f / (1.0f + expf(-ma1));
    }
}

// ---------------------------------------------------------------------------
extern "C" void kernel_launch(void* const* d_in, const int* in_sizes, int n_in,
                              void* d_out, int out_size) {
    const float* x      = (const float*)d_in[0];
    const float* W_in   = (const float*)d_in[1];
    const float* b_in   = (const float*)d_in[2];
    const float* beta1  = (const float*)d_in[3];
    const float* thr1   = (const float*)d_in[4];
    const float* W_h    = (const float*)d_in[5];
    const float* b_h    = (const float*)d_in[6];
    const float* beta2  = (const float*)d_in[7];
    const float* thr2   = (const float*)d_in[8];
    const float* W_h1   = (const float*)d_in[9];
    const float* b_h1   = (const float*)d_in[10];
    const float* W_f    = (const float*)d_in[11];
    const float* b_f    = (const float*)d_in[12];
    const float* beta_f = (const float*)d_in[13];
    const float* W_a    = (const float*)d_in[14];
    const float* b_a    = (const float*)d_in[15];
    const float* beta_a = (const float*)d_in[16];
    float* out = (float*)d_out;

    cudaFuncSetAttribute(snn_rec, cudaFuncAttributeMaxDynamicSharedMemorySize,
                         SMEM_BYTES);
    cudaFuncSetAttribute(precompute_cur1,
                         cudaFuncAttributeMaxDynamicSharedMemorySize, 65536);

    dummy_k<<<1, 1>>>();
    prep_weights<<<dim3(8, 8, 4), dim3(32, 8)>>>(W_in, W_h, W_h1, W_f, W_a);
    precompute_cur1<<<dim3(2, BATCH), 512, 65536>>>(x);
    snn_rec<<<BATCH / 8, 512, SMEM_BYTES>>>(b_in, beta1, thr1, b_h, beta2, thr2,
                                            b_h1, b_f, beta_f, b_a, beta_a, out);
}

// round 11
// speedup vs baseline: 1.5124x; 1.1026x over previous
#include <cuda_runtime.h>
#include <math.h>

#define BATCH  1024
#define DIM    256
#define TSTEPS 128
#define HID    256
#define NOUT   64
#define JC     80     // j-rows of each hidden matrix cached in smem

__device__ float g_cur1[(size_t)TSTEPS * BATCH * HID];  // [t][b][h]
__device__ float g_WTin[DIM * HID];        // [d][h]
__device__ float g_WTh [HID * HID];        // [j][h]
__device__ float g_WTh1[HID * HID];        // [j][h]
__device__ float g_Wfa [HID * NOUT * 2];   // [j][o][2] (wf, wa)

typedef unsigned long long ull;

__device__ __forceinline__ void ffma2(ull& acc, ull a, ull b) {
    asm("fma.rn.f32x2 %0, %1, %2, %0;" : "+l"(acc) : "l"(a), "l"(b));
}
__device__ __forceinline__ ull mul2(ull a, ull b) {
    ull r; asm("mul.rn.f32x2 %0, %1, %2;" : "=l"(r) : "l"(a), "l"(b)); return r;
}
__device__ __forceinline__ ull add2(ull a, ull b) {
    ull r; asm("add.rn.f32x2 %0, %1, %2;" : "=l"(r) : "l"(a), "l"(b)); return r;
}
__device__ __forceinline__ ull pack2(float x, float y) {
    ull r; asm("mov.b64 %0, {%1, %2};" : "=l"(r) : "f"(x), "f"(y)); return r;
}
__device__ __forceinline__ void unpack2(ull v, float& x, float& y) {
    asm("mov.b64 {%0, %1}, %2;" : "=f"(x), "=f"(y) : "l"(v));
}
__device__ __forceinline__ float clamp01(float v) {
    return fminf(fmaxf(v, 0.0f), 1.0f);
}

__global__ void dummy_k() {}

// ---------------------------------------------------------------------------
__global__ void prep_weights(const float* __restrict__ W_in,
                             const float* __restrict__ W_h,
                             const float* __restrict__ W_h1,
                             const float* __restrict__ W_f,
                             const float* __restrict__ W_a) {
    if (blockIdx.z == 3) {
        int idx = (blockIdx.y * 8 + blockIdx.x) * 256 + threadIdx.y * 32 + threadIdx.x;
        int j = idx >> 6, oo = idx & 63;
        g_Wfa[idx * 2]     = W_f[oo * HID + j];
        g_Wfa[idx * 2 + 1] = W_a[oo * HID + j];
        return;
    }
    __shared__ float tile[32][33];
    const float* in; float* out;
    switch (blockIdx.z) {
        case 0:  in = W_in; out = g_WTin; break;
        case 1:  in = W_h;  out = g_WTh;  break;
        default: in = W_h1; out = g_WTh1; break;
    }
    int c0 = blockIdx.x * 32, r0 = blockIdx.y * 32;
    int tx = threadIdx.x, ty = threadIdx.y;
    #pragma unroll
    for (int k = 0; k < 32; k += 8)
        tile[ty + k][tx] = in[(r0 + ty + k) * 256 + (c0 + tx)];
    __syncthreads();
    #pragma unroll
    for (int k = 0; k < 32; k += 8)
        out[(c0 + ty + k) * 256 + (r0 + tx)] = tile[tx][ty + k];
}

// ---------------------------------------------------------------------------
// cur1[t][b][h] = sum_d x[b][d][t]*W_in[h][d].  (unchanged — bit-exact)
// ---------------------------------------------------------------------------
__global__ void __launch_bounds__(512) precompute_cur1(const float* __restrict__ x) {
    extern __shared__ __align__(16) float xS[];
    ull* xsu = reinterpret_cast<ull*>(xS);
    const int tid = threadIdx.x;
    const int t0  = blockIdx.x * 64;
    const int b   = blockIdx.y;

    {
        int d = tid >> 1, th = (tid & 1) * 32;
        const float4* xp = reinterpret_cast<const float4*>(
            x + ((size_t)b * DIM + d) * TSTEPS + t0 + th);
        #pragma unroll
        for (int q = 0; q < 8; ++q) {
            float4 v = __ldg(xp + q);
            xsu[d * 32 + th / 2 + 2 * q]     = pack2(v.x, v.y);
            xsu[d * 32 + th / 2 + 2 * q + 1] = pack2(v.z, v.w);
        }
    }
    __syncthreads();

    const int hp = tid & 127;
    const int tg = tid >> 7;
    ull acc[16];
    #pragma unroll
    for (int i = 0; i < 16; ++i) acc[i] = 0ull;

    const ull* gw = reinterpret_cast<const ull*>(g_WTin) + hp;
    #pragma unroll 1
    for (int blk = 0; blk < 32; ++blk) {
        ull wv[8];
        #pragma unroll
        for (int i = 0; i < 8; ++i)
            wv[i] = __ldg(gw + (blk * 8 + i) * 128);
        #pragma unroll
        for (int i = 0; i < 8; ++i) {
            const int j = blk * 8 + i;
            float w0, w1; unpack2(wv[i], w0, w1);
            ull wa = pack2(w0, w0), wb = pack2(w1, w1);
            const ull* xr = xsu + j * 32 + tg * 8;
            #pragma unroll
            for (int tp = 0; tp < 8; ++tp) {
                ull xv = xr[tp];
                ffma2(acc[tp],     xv, wa);
                ffma2(acc[8 + tp], xv, wb);
            }
        }
    }
    #pragma unroll
    for (int tp = 0; tp < 8; ++tp) {
        float a0, a1, b0, b1;
        unpack2(acc[tp], a0, a1);
        unpack2(acc[8 + tp], b0, b1);
        int t = t0 + tg * 16 + 2 * tp;
        *reinterpret_cast<ull*>(g_cur1 + ((size_t)t * BATCH + b) * HID + 2 * hp)
            = pack2(a0, b0);
        *reinterpret_cast<ull*>(g_cur1 + ((size_t)(t + 1) * BATCH + b) * HID + 2 * hp)
            = pack2(a1, b1);
    }
}

// ---------------------------------------------------------------------------
// Uncached-j helpers: blocks of 16, register double-buffered.
// ---------------------------------------------------------------------------
__device__ __forceinline__ void ldblk16(ull* buf, const ull* gb, int blk) {
    #pragma unroll
    for (int i = 0; i < 16; ++i)
        buf[i] = __ldg(gb + (JC + blk * 16 + i) * 128);
}
__device__ __forceinline__ void useblk16(const ull* buf, const float* sInb,
                                         int blk, ull* acc) {
    #pragma unroll
    for (int i = 0; i < 16; ++i) {
        float w0, w1; unpack2(buf[i], w0, w1);
        ull wa = pack2(w0, w0), wb = pack2(w1, w1);
        ulonglong2 sv = *reinterpret_cast<const ulonglong2*>(
            sInb + (JC + blk * 16 + i) * 8);
        ffma2(acc[0], sv.x, wa); ffma2(acc[1], sv.y, wa);
        ffma2(acc[2], sv.x, wb); ffma2(acc[3], sv.y, wb);
    }
}

// ---------------------------------------------------------------------------
// Hidden layer: thread owns 2 h x 4 rows. Chains serial over j — bit-exact.
// ---------------------------------------------------------------------------
__device__ __forceinline__ void layerX(
    const float* sW, const ull* __restrict__ gWp, const float* sIn,
    int rg, int hp,
    float bias0, float bias1, float bc0, float bc1, float thr0, float thr1,
    float* m /*[hh*4+r]*/, float* sOut)
{
    ull acc[4] = {0ull, 0ull, 0ull, 0ull};
    const float* sInb = sIn + rg * 4;
    const ull* sWp = reinterpret_cast<const ull*>(sW) + hp;
    #pragma unroll 8
    for (int j = 0; j < JC; ++j) {
        float w0, w1; unpack2(sWp[j * 128], w0, w1);
        ull wa = pack2(w0, w0), wb = pack2(w1, w1);
        ulonglong2 sv = *reinterpret_cast<const ulonglong2*>(sInb + j * 8);
        ffma2(acc[0], sv.x, wa); ffma2(acc[1], sv.y, wa);
        ffma2(acc[2], sv.x, wb); ffma2(acc[3], sv.y, wb);
    }
    // 176 uncached rows = 11 blocks of 16, double-buffered
    const ull* gb = gWp + hp;
    ull bufA[16], bufB[16];
    ldblk16(bufA, gb, 0);
    #pragma unroll
    for (int b2 = 0; b2 < 5; ++b2) {
        ldblk16(bufB, gb, 2 * b2 + 1);
        useblk16(bufA, sInb, 2 * b2, acc);
        ldblk16(bufA, gb, 2 * b2 + 2);      // b2=4 -> blk 10 (last)
        useblk16(bufB, sInb, 2 * b2 + 1, acc);
    }
    useblk16(bufA, sInb, 10, acc);

    #pragma unroll
    for (int hh = 0; hh < 2; ++hh) {
        float bias = hh ? bias1 : bias0;
        float bc   = hh ? bc1 : bc0;
        float thr  = hh ? thr1 : thr0;
        ull svp[2];
        #pragma unroll
        for (int p = 0; p < 2; ++p) {
            float c0, c1; unpack2(acc[hh * 2 + p], c0, c1);
            float* mm = m + hh * 4 + 2 * p;
            float ca = __fadd_rn(c0, bias);
            float cb = __fadd_rn(c1, bias);
            float ra = (mm[0] > thr) ? thr : 0.0f;     // reset from PREV mem
            float rb = (mm[1] > thr) ? thr : 0.0f;
            float na = __fsub_rn(__fadd_rn(__fmul_rn(bc, mm[0]), ca), ra);
            float nb = __fsub_rn(__fadd_rn(__fmul_rn(bc, mm[1]), cb), rb);
            mm[0] = na; mm[1] = nb;
            svp[p] = pack2((na > thr) ? 1.0f : 0.0f, (nb > thr) ? 1.0f : 0.0f);
        }
        ulonglong2 v; v.x = svp[0]; v.y = svp[1];
        *reinterpret_cast<ulonglong2*>(sOut + (2 * hp + hh) * 8 + rg * 4) = v;
    }
}

// ---------------------------------------------------------------------------
// Recurrent kernel: 128 CTAs x 512 threads.
//  A (warps 0-7): NEW lane map: hp = warp*16 + (lane>>1), rg = lane&1.
//    Each warp covers 32 h x all 8 rows -> weight reads 128B/warp/j (1 phase)
//    instead of 256B (2 phases). Arithmetic per (h,row) chain unchanged.
//  B (warps 8-15): output-LI GEMM for step k-1; Wfa from global (L2-hot)
// ---------------------------------------------------------------------------
#define SMEM_FLOATS (2 * JC * HID + 4 * 2048 + 4096)
#define SMEM_BYTES  (SMEM_FLOATS * 4)

__global__ void __launch_bounds__(512, 1) snn_rec(
    const float* __restrict__ b_in,  const float* __restrict__ beta1,
    const float* __restrict__ thr1,
    const float* __restrict__ b_h,   const float* __restrict__ beta2,
    const float* __restrict__ thr2,
    const float* __restrict__ b_h1,
    const float* __restrict__ b_f,   const float* __restrict__ beta_f,
    const float* __restrict__ b_a,   const float* __restrict__ beta_a,
    float* __restrict__ out)
{
    extern __shared__ __align__(16) float dsm[];
    float* sWh  = dsm;
    float* sWh1 = sWh + JC * HID;
    float* s1P  = sWh1 + JC * HID;
    float* s2P  = s1P + 2048;
    float* s3a  = s2P + 2048;
    float* s3b  = s3a + 2048;
    ull*   scr  = reinterpret_cast<ull*>(s3b + 2048);

    const int tid = threadIdx.x;
    const int b0  = blockIdx.x * 8;

    for (int i = tid; i < JC * HID; i += 512) {
        sWh[i]  = g_WTh[i];
        sWh1[i] = g_WTh1[i];
    }

    if (tid < 256) {
        // ===================== A role =====================
        const int w    = tid >> 5;           // warp 0..7
        const int lane = tid & 31;
        const int hp   = w * 16 + (lane >> 1);   // 0..127
        const int rg   = lane & 1;               // row-half
        const int h0 = 2 * hp, h1 = h0 + 1;
        const float bin0 = b_in[h0],  bin1 = b_in[h1];
        const float b1c0 = clamp01(beta1[h0]), b1c1 = clamp01(beta1[h1]);
        const float t10 = thr1[h0],  t11 = thr1[h1];
        const float bh0 = b_h[h0],   bh1 = b_h[h1];
        const float b2c0 = clamp01(beta2[h0]), b2c1 = clamp01(beta2[h1]);
        const float t20 = thr2[h0],  t21 = thr2[h1];
        const float bh10 = b_h1[h0], bh11 = b_h1[h1];

        float m1[8], m2[8], m3[8];
        #pragma unroll
        for (int i = 0; i < 8; ++i) { m1[i] = 0.f; m2[i] = 0.f; m3[i] = 0.f; }

        const int rowbase = b0 + rg * 4;
        ull c1p[4];
        #pragma unroll
        for (int r = 0; r < 4; ++r)
            c1p[r] = __ldg(reinterpret_cast<const ull*>(
                g_cur1 + ((size_t)0 * BATCH + rowbase + r) * HID + h0));

        __syncthreads();   // weight caches ready

        const ull* gWh  = reinterpret_cast<const ull*>(g_WTh);
        const ull* gWh1 = reinterpret_cast<const ull*>(g_WTh1);

        for (int k = 0; k <= TSTEPS; ++k) {
            if (k < TSTEPS) {
                // ---- LIF layer 1: 2h x 4 rows ----
                ull sv0[2], sv1[2];
                #pragma unroll
                for (int p = 0; p < 2; ++p) {
                    float ca0, cb0, ca1, cb1;
                    unpack2(c1p[2 * p],     ca0, ca1);   // row 2p:   (h0, h1)
                    unpack2(c1p[2 * p + 1], cb0, cb1);   // row 2p+1: (h0, h1)
                    float x0 = __fadd_rn(ca0, bin0);
                    float x1 = __fadd_rn(cb0, bin0);
                    float r0 = (m1[2 * p] > t10) ? t10 : 0.0f;
                    float r1 = (m1[2 * p + 1] > t10) ? t10 : 0.0f;
                    float n0 = __fsub_rn(__fadd_rn(__fmul_rn(b1c0, m1[2 * p]), x0), r0);
                    float n1 = __fsub_rn(__fadd_rn(__fmul_rn(b1c0, m1[2 * p + 1]), x1), r1);
                    m1[2 * p] = n0; m1[2 * p + 1] = n1;
                    sv0[p] = pack2((n0 > t10) ? 1.0f : 0.0f, (n1 > t10) ? 1.0f : 0.0f);
                    float y0 = __fadd_rn(ca1, bin1);
                    float y1 = __fadd_rn(cb1, bin1);
                    float s0 = (m1[4 + 2 * p] > t11) ? t11 : 0.0f;
                    float s1 = (m1[4 + 2 * p + 1] > t11) ? t11 : 0.0f;
                    float q0 = __fsub_rn(__fadd_rn(__fmul_rn(b1c1, m1[4 + 2 * p]), y0), s0);
                    float q1 = __fsub_rn(__fadd_rn(__fmul_rn(b1c1, m1[4 + 2 * p + 1]), y1), s1);
                    m1[4 + 2 * p] = q0; m1[4 + 2 * p + 1] = q1;
                    sv1[p] = pack2((q0 > t11) ? 1.0f : 0.0f, (q1 > t11) ? 1.0f : 0.0f);
                }
                {
                    ulonglong2 v;
                    v.x = sv0[0]; v.y = sv0[1];
                    *reinterpret_cast<ulonglong2*>(s1P + h0 * 8 + rg * 4) = v;
                    v.x = sv1[0]; v.y = sv1[1];
                    *reinterpret_cast<ulonglong2*>(s1P + h1 * 8 + rg * 4) = v;
                }
                if (k + 1 < TSTEPS) {
                    #pragma unroll
                    for (int r = 0; r < 4; ++r)
                        c1p[r] = __ldg(reinterpret_cast<const ull*>(
                            g_cur1 + ((size_t)(k + 1) * BATCH + rowbase + r) * HID + h0));
                }
                asm volatile("bar.sync 1, 256;" ::: "memory");

                layerX(sWh, gWh, s1P, rg, hp,
                       bh0, bh1, b2c0, b2c1, t20, t21, m2, s2P);
                asm volatile("bar.sync 1, 256;" ::: "memory");

                float* s3 = (k & 1) ? s3b : s3a;
                layerX(sWh1, gWh1, s2P, rg, hp,
                       bh10, bh11, b2c0, b2c1, t20, t21, m3, s3);  // bug preserved
            }
            __syncthreads();   // publish s3(k) to B
        }
    } else {
        // ===================== B role =====================
        const int bt = tid - 256;
        const int o  = bt & 63;
        const int q  = bt >> 6;
        const ull bias_fa = pack2(b_f[o], b_a[o]);
        const ull beta_fa = pack2(clamp01(beta_f[o]), clamp01(beta_a[o]));
        ull macc0 = pack2(0.f, 0.f), macc1 = macc0;
        const ull* wrow = reinterpret_cast<const ull*>(g_Wfa);

        __syncthreads();

        for (int k = 0; k <= TSTEPS; ++k) {
            if (k >= 1) {
                const float* s3 = ((k - 1) & 1) ? s3b : s3a;
                ull accF[4] = {0ull, 0ull, 0ull, 0ull};
                ull accA[4] = {0ull, 0ull, 0ull, 0ull};
                const int j0 = q * 64;
                #pragma unroll 8
                for (int jj = 0; jj < 64; ++jj) {
                    int j = j0 + jj;
                    ull wv = __ldg(wrow + j * 64 + o);
                    float wf, wa; unpack2(wv, wf, wa);
                    ull wf2 = pack2(wf, wf), wa2 = pack2(wa, wa);
                    const ulonglong2* sp =
                        reinterpret_cast<const ulonglong2*>(s3 + j * 8);
                    ulonglong2 sA = sp[0], sB = sp[1];
                    ffma2(accF[0], sA.x, wf2); ffma2(accF[1], sA.y, wf2);
                    ffma2(accF[2], sB.x, wf2); ffma2(accF[3], sB.y, wf2);
                    ffma2(accA[0], sA.x, wa2); ffma2(accA[1], sA.y, wa2);
                    ffma2(accA[2], sB.x, wa2); ffma2(accA[3], sB.y, wa2);
                }
                #pragma unroll
                for (int r2 = 0; r2 < 4; ++r2) {
                    scr[r2 * 256 + q * 64 + o]        = accF[r2];
                    scr[1024 + r2 * 256 + q * 64 + o] = accA[r2];
                }
                asm volatile("bar.sync 2, 256;" ::: "memory");
                ull Fs = pack2(0.f, 0.f), As = Fs;
                #pragma unroll
                for (int qq = 0; qq < 4; ++qq) {
                    Fs = add2(Fs, scr[q * 256 + qq * 64 + o]);
                    As = add2(As, scr[1024 + q * 256 + qq * 64 + o]);
                }
                float f0, f1, a0, a1;
                unpack2(Fs, f0, f1);
                unpack2(As, a0, a1);
                macc0 = add2(mul2(beta_fa, macc0), add2(pack2(f0, a0), bias_fa));
                macc1 = add2(mul2(beta_fa, macc1), add2(pack2(f1, a1), bias_fa));
            }
            __syncthreads();
        }

        float mf0, ma0, mf1, ma1;
        unpack2(macc0, mf0, ma0);
        unpack2(macc1, mf1, ma1);
        int row = b0 + 2 * q;
        out[(size_t)row * NOUT + o]                              = 1.0f / (1.0f + expf(-mf0));
        out[(size_t)(row + 1) * NOUT + o]                        = 1.0f / (1.0f + expf(-mf1));
        out[(size_t)BATCH * NOUT + (size_t)row * NOUT + o]       = 1.0f / (1.0f + expf(-ma0));
        out[(size_t)BATCH * NOUT + (size_t)(row + 1) * NOUT + o] = 1.0f / (1.0f + expf(-ma1));
    }
}

// ---------------------------------------------------------------------------
extern "C" void kernel_launch(void* const* d_in, const int* in_sizes, int n_in,
                              void* d_out, int out_size) {
    const float* x      = (const float*)d_in[0];
    const float* W_in   = (const float*)d_in[1];
    const float* b_in   = (const float*)d_in[2];
    const float* beta1  = (const float*)d_in[3];
    const float* thr1   = (const float*)d_in[4];
    const float* W_h    = (const float*)d_in[5];
    const float* b_h    = (const float*)d_in[6];
    const float* beta2  = (const float*)d_in[7];
    const float* thr2   = (const float*)d_in[8];
    const float* W_h1   = (const float*)d_in[9];
    const float* b_h1   = (const float*)d_in[10];
    const float* W_f    = (const float*)d_in[11];
    const float* b_f    = (const float*)d_in[12];
    const float* beta_f = (const float*)d_in[13];
    const float* W_a    = (const float*)d_in[14];
    const float* b_a    = (const float*)d_in[15];
    const float* beta_a = (const float*)d_in[16];
    float* out = (float*)d_out;

    cudaFuncSetAttribute(snn_rec, cudaFuncAttributeMaxDynamicSharedMemorySize,
                         SMEM_BYTES);
    cudaFuncSetAttribute(precompute_cur1,
                         cudaFuncAttributeMaxDynamicSharedMemorySize, 65536);

    dummy_k<<<1, 1>>>();
    prep_weights<<<dim3(8, 8, 4), dim3(32, 8)>>>(W_in, W_h, W_h1, W_f, W_a);
    precompute_cur1<<<dim3(2, BATCH), 512, 65536>>>(x);
    snn_rec<<<BATCH / 8, 512, SMEM_BYTES>>>(b_in, beta1, thr1, b_h, beta2, thr2,
                                            b_h1, b_f, beta_f, b_a, beta_a, out);
}